// round 11
// baseline (speedup 1.0000x reference)
#include <cuda_runtime.h>
#include <math.h>

#define NN 16384
#define NE 262144
#define NF 128
#define ND 64
#define NC 40
#define RK 16
#define MAXDEG 64
#define ZOFF16 (NN * 16)   // float4-unit offset of the permanent zero row

typedef unsigned long long u64t;

// ---------------- packed f32x2 helpers (Blackwell) --------------------------
__device__ __forceinline__ u64t pk2(float lo, float hi) {
    u64t r; asm("mov.b64 %0, {%1, %2};" : "=l"(r) : "f"(lo), "f"(hi)); return r;
}
__device__ __forceinline__ void upk2(u64t v, float& lo, float& hi) {
    asm("mov.b64 {%0, %1}, %2;" : "=f"(lo), "=f"(hi) : "l"(v));
}
__device__ __forceinline__ void ffma2(u64t& d, u64t a, u64t b) {
    asm("fma.rn.f32x2 %0, %1, %2, %0;" : "+l"(d) : "l"(a), "l"(b));
}
__device__ __forceinline__ void fadd2(u64t& d, u64t a) {
    asm("add.rn.f32x2 %0, %0, %1;" : "+l"(d) : "l"(a));
}
__device__ __forceinline__ void pdl_wait() {
    asm volatile("griddepcontrol.wait;" ::: "memory");
}

// ------------- scratch (device globals; zero at module load) ----------------
__device__ float g_xl [(NN + 1) * ND];   // row NN: permanent zero row
__device__ float g_xr [NN * ND];
__device__ float g_h1 [NN * ND];
__device__ float g_h1l[(NN + 1) * ND];   // row NN: permanent zero row
__device__ float g_h1r[NN * ND];
__device__ float g_h2 [NN * ND];
__device__ float g_phi[NN * RK];
__device__ float g_T  [RK * 65];
__device__ int   g_deg[NN];              // zero at load; tail2 re-zeros
__device__ int   g_ell[NN * MAXDEG];     // stores src*16 (float4-unit offsets)
__device__ unsigned g_sync;              // monotonic barrier counter

// c_k = sqrt(2^k / k!)
__constant__ float c_coef[RK] = {
    1.0f,          1.41421356f,  1.41421356f,  1.15470054f,
    0.81649658f,   0.51639778f,  0.29814240f,  0.15936387f,
    0.07968194f,   0.03756241f,  0.01679842f,  0.00716286f,
    0.00292422f,   0.00114698f,  4.33517e-4f,  1.58298e-4f};

// ---------------- grid-wide barrier (monotonic counter, no reset) -----------
__device__ __forceinline__ void grid_sync(unsigned G) {
    __syncthreads();
    if (threadIdx.x == 0) {
        __threadfence();
        unsigned old = atomicAdd(&g_sync, 1u);
        unsigned target = old / G * G + G;
        while ((int)(*(volatile unsigned*)&g_sync - target) < 0) {
            __nanosleep(64);
        }
        __threadfence();
    }
    __syncthreads();
}

// ---- dual GEMM body: outl = A @ Wl, outr = A @ Wr  (A:[NN,K], W:[K,64]) ----
// smem pre-packed: sA holds duplicated pairs (a,a) as u64; sW read as u64
// pairs directly. Inner loop: 4 x LDS.128 + 16 x FFMA2, no packing.
template <int K>
__device__ __forceinline__ void gemm_body(const float* __restrict__ A,
                                          const float* __restrict__ Wl,
                                          const float* __restrict__ Wr,
                                          float* __restrict__ outl,
                                          float* __restrict__ outr,
                                          int mblk, float* sA, float* sW) {
    constexpr int KC = 16;
    constexpr int SAS = 136;          // floats per sA row (64 dup pairs + pad)
    const int tid = threadIdx.x;
    const int mg = tid >> 4;
    const int ng = tid & 15;
    const int m_base = mblk * 64;

    u64t acc[4][4];
#pragma unroll
    for (int i = 0; i < 4; i++)
#pragma unroll
        for (int j = 0; j < 4; j++) acc[i][j] = 0ull;

    for (int kk = 0; kk < K; kk += KC) {
        __syncthreads();
        // A chunk: 64 rows x 16 k, stored as duplicated (a,a) float2
#pragma unroll
        for (int j = 0; j < 4; j++) {
            int i = tid + 256 * j;
            int m = i >> 4;
            int k = i & 15;
            float v = __ldg(A + (long)(m_base + m) * K + kk + k);
            *reinterpret_cast<float2*>(sA + k * SAS + 2 * m) = make_float2(v, v);
        }
        // W chunk: 16 k x 128 n
#pragma unroll
        for (int j = 0; j < 8; j++) {
            int i = tid + 256 * j;
            int k = i >> 7;
            int n = i & 127;
            float w = (n < 64) ? __ldg(Wl + (long)(kk + k) * 64 + n)
                               : __ldg(Wr + (long)(kk + k) * 64 + (n - 64));
            sW[k * 128 + n] = w;
        }
        __syncthreads();

#pragma unroll
        for (int k = 0; k < KC; k++) {
            const ulonglong2* ap2 =
                reinterpret_cast<const ulonglong2*>(sA + k * SAS) + mg * 2;
            const ulonglong2* wp2 =
                reinterpret_cast<const ulonglong2*>(sW + k * 128) + ng * 2;
            ulonglong2 A0 = ap2[0], A1 = ap2[1];
            ulonglong2 W0 = wp2[0], W1 = wp2[1];
            u64t ap[4] = {A0.x, A0.y, A1.x, A1.y};
            u64t wp[4] = {W0.x, W0.y, W1.x, W1.y};
#pragma unroll
            for (int i = 0; i < 4; i++)
#pragma unroll
                for (int j = 0; j < 4; j++) ffma2(acc[i][j], ap[i], wp[j]);
        }
    }

    float* outp = (ng < 8) ? outl : outr;
    int cb = (ng & 7) * 8;
#pragma unroll
    for (int i = 0; i < 4; i++) {
        long r = m_base + mg * 4 + i;
        float o0, o1, o2, o3, o4v, o5, o6, o7;
        upk2(acc[i][0], o0, o1); upk2(acc[i][1], o2, o3);
        upk2(acc[i][2], o4v, o5); upk2(acc[i][3], o6, o7);
        float4* o4 = reinterpret_cast<float4*>(outp + r * ND + cb);
        o4[0] = make_float4(o0, o1, o2, o3);
        o4[1] = make_float4(o4v, o5, o6, o7);
    }
}

// ---- half-warp gather: warp handles 2 rows, 16 lanes per row, float4 -------
// batch-4 loads (proven best: 32 regs, occ ~72%)
template <bool RELU, bool PHI>
__device__ __forceinline__ void gather2rows(int base_row,
                                            const float* __restrict__ val,
                                            const float* __restrict__ selfp,
                                            const float* __restrict__ bias,
                                            float* __restrict__ out,
                                            float ainv, const float4* aux4s) {
    int lane = threadIdx.x & 31;
    int hsel = lane & 16;        // 0 or 16
    int lane16 = lane & 15;
    int row = base_row + (lane >> 4);
    int deg = __ldg(g_deg + row);
    const ulonglong2* v16 = reinterpret_cast<const ulonglong2*>(val);

    u64t a0 = 0ull, a1 = 0ull, a2 = 0ull, a3 = 0ull;
#pragma unroll 1
    for (int c = 0; c < MAXDEG; c += 16) {
        int dc = min(max(deg - c, 0), 16);
        int kmax = max(dc, __shfl_xor_sync(0xffffffffu, dc, 16));
        if (kmax == 0) break;
        int j = (lane16 < dc) ? __ldg(g_ell + row * MAXDEG + c + lane16) : ZOFF16;
        int kr = (kmax + 3) & ~3;
#pragma unroll 1
        for (int k = 0; k < kr; k += 4) {
            int b0 = __shfl_sync(0xffffffffu, j, hsel + k);
            int b1 = __shfl_sync(0xffffffffu, j, hsel + k + 1);
            int b2 = __shfl_sync(0xffffffffu, j, hsel + k + 2);
            int b3 = __shfl_sync(0xffffffffu, j, hsel + k + 3);
            ulonglong2 x0 = __ldg(v16 + b0 + lane16);
            ulonglong2 x1 = __ldg(v16 + b1 + lane16);
            ulonglong2 x2 = __ldg(v16 + b2 + lane16);
            ulonglong2 x3 = __ldg(v16 + b3 + lane16);
            fadd2(a0, x0.x); fadd2(a1, x0.y);
            fadd2(a2, x1.x); fadd2(a3, x1.y);
            fadd2(a0, x2.x); fadd2(a1, x2.y);
            fadd2(a2, x3.x); fadd2(a3, x3.y);
        }
    }
    fadd2(a0, a2); fadd2(a1, a3);

    float f0, f1, f2, f3;
    upk2(a0, f0, f1); upk2(a1, f2, f3);
    float inv = 1.f / fmaxf((float)deg, 1.f);
    float4 b = __ldg(reinterpret_cast<const float4*>(bias) + lane16);
    float4 s = __ldg(reinterpret_cast<const float4*>(selfp) + row * 16 + lane16);
    float4 r = make_float4(f0 * inv + b.x + s.x, f1 * inv + b.y + s.y,
                           f2 * inv + b.z + s.z, f3 * inv + b.w + s.w);
    if (RELU) {
        r.x = fmaxf(r.x, 0.f); r.y = fmaxf(r.y, 0.f);
        r.z = fmaxf(r.z, 0.f); r.w = fmaxf(r.w, 0.f);
    }
    reinterpret_cast<float4*>(out)[row * 16 + lane16] = r;

    if (PHI) {
        float4 av = aux4s[lane16];
        float dot = r.x * av.x + r.y * av.y + r.z * av.z + r.w * av.w;
        float nn2 = r.x * r.x + r.y * r.y + r.z * r.z + r.w * r.w;
#pragma unroll
        for (int o = 8; o; o >>= 1) {              // reduce within each half
            dot += __shfl_xor_sync(0xffffffffu, dot, o);
            nn2 += __shfl_xor_sync(0xffffffffu, nn2, o);
        }
        float sc = dot * ainv / fmaxf(sqrtf(nn2), 1e-8f);
        float e = expf(-sc * sc);
        float sc2 = sc * sc, sc4 = sc2 * sc2, sc8 = sc4 * sc4;
        float p = 1.f;
        if (lane16 & 1) p *= sc;
        if (lane16 & 2) p *= sc2;
        if (lane16 & 4) p *= sc4;
        if (lane16 & 8) p *= sc8;
        g_phi[row * RK + lane16] = e * c_coef[lane16] * p;
    }
}

// ---- launch 1: blocks [0,256) gemm1, blocks [256,1280) ELL fill ------------
__global__ __launch_bounds__(256) void fused1(const float* __restrict__ x,
                                              const float* __restrict__ W1l,
                                              const float* __restrict__ W1r,
                                              const int* __restrict__ ei) {
    __shared__ __align__(16) float sA[16 * 136];
    __shared__ __align__(16) float sW[16 * 128];
    if (blockIdx.x < NN / 64) {
        gemm_body<NF>(x, W1l, W1r, g_xl, g_xr, blockIdx.x, sA, sW);
    } else {
        int t = (blockIdx.x - NN / 64) * 256 + threadIdx.x;
        int src = __ldg(ei + t);
        int dst = __ldg(ei + NE + t);
        int slot = atomicAdd(g_deg + dst, 1) & (MAXDEG - 1);
        g_ell[dst * MAXDEG + slot] = src * 16;
    }
}

// ---- launch 2: layer-1 gather + relu epilogue (also zeroes g_T) ------------
__global__ __launch_bounds__(256) void gather1_kernel(const float* __restrict__ b1) {
    pdl_wait();
    if (blockIdx.x == 0)
        for (int i = threadIdx.x; i < RK * 65; i += 256) g_T[i] = 0.f;
    int base = (blockIdx.x * 8 + (threadIdx.x >> 5)) * 2;
    gather2rows<true, false>(base, g_xl, g_xr, b1, g_h1, 0.f, nullptr);
}

// ---- launch 3: gemm2 --------------------------------------------------------
__global__ __launch_bounds__(256) void gemm2_kernel(const float* __restrict__ W2l,
                                                    const float* __restrict__ W2r) {
    pdl_wait();
    __shared__ __align__(16) float sA[16 * 136];
    __shared__ __align__(16) float sW[16 * 128];
    gemm_body<ND>(g_h1, W2l, W2r, g_h1l, g_h1r, blockIdx.x, sA, sW);
}

// ---- launch 4: layer-2 gather + epilogue + phi ------------------------------
__global__ __launch_bounds__(256) void gather2_kernel(const float* __restrict__ b2,
                                                      const float* __restrict__ aux) {
    pdl_wait();
    __shared__ float4 aux4s[16];
    __shared__ float s_ainv;
    int tid = threadIdx.x;
    if (tid < 16) aux4s[tid] = __ldg(reinterpret_cast<const float4*>(aux) + tid);
    __syncthreads();
    if (tid < 16) {
        float4 a = aux4s[tid];
        float ss = a.x * a.x + a.y * a.y + a.z * a.z + a.w * a.w;
#pragma unroll
        for (int o = 8; o; o >>= 1) ss += __shfl_xor_sync(0x0000ffffu, ss, o);
        if (tid == 0) s_ainv = 1.f / fmaxf(sqrtf(ss), 1e-8f);
    }
    __syncthreads();
    int base = (blockIdx.x * 8 + (tid >> 5)) * 2;
    gather2rows<false, true>(base, g_h1l, g_h1r, b2, g_h2, s_ainv, aux4s);
}

// ---- launch 5 (fused): phiT -> grid barrier -> classifier -------------------
// 128 blocks x 256 threads. Stage E: 1024 warp-units x 16 rows.
// Stage F: 2 threads per row (128 rows per block).
__global__ __launch_bounds__(256) void tail2(const float* __restrict__ Wc,
                                             const float* __restrict__ bc,
                                             float* __restrict__ out) {
    pdl_wait();
    __shared__ __align__(16) float sp[6300];
    int tid = threadIdx.x;
    int lane = tid & 31;

    // ---- stage E: T = Phi^T [h2 | 1] ----------------------------------------
    {
        int gw = blockIdx.x * 8 + (tid >> 5);   // 1024 units x 16 rows
        float accA[RK], accB[RK];
#pragma unroll
        for (int k = 0; k < RK; k++) { accA[k] = 0.f; accB[k] = 0.f; }
        float accD = 0.f;
        int r0 = gw * 16;
#pragma unroll 2
        for (int r = r0; r < r0 + 16; r++) {
            float pv = (lane < RK) ? g_phi[(long)r * RK + lane] : 0.f;
            float v0 = g_h2[(long)r * ND + lane];
            float v1 = g_h2[(long)r * ND + 32 + lane];
            accD += pv;
#pragma unroll
            for (int k = 0; k < RK; k++) {
                float pk = __shfl_sync(0xffffffffu, pv, k);
                accA[k] += pk * v0;
                accB[k] += pk * v1;
            }
        }
#pragma unroll
        for (int k = 0; k < RK; k++) {
            atomicAdd(&g_T[k * 65 + lane], accA[k]);
            atomicAdd(&g_T[k * 65 + 32 + lane], accB[k]);
        }
        if (lane < RK) atomicAdd(&g_T[lane * 65 + 64], accD);
    }

    grid_sync(128);

    // ---- stage F: z = Phi T / den; out = [h2|z] @ Wc + bc; g_deg reset ------
    {
        float* Ts = sp;                                 // 1040 floats
        u64t* Wp = reinterpret_cast<u64t*>(sp + 1056);  // 2560 u64
        u64t* bp = reinterpret_cast<u64t*>(sp + 6176);  // 20 u64
        for (int i = tid; i < RK * 65; i += 256) Ts[i] = g_T[i];
        for (int i = tid; i < 128 * 20; i += 256) {
            int d = i / 20, c = i % 20;
            Wp[i] = pk2(__ldg(Wc + d * NC + 2 * c), __ldg(Wc + d * NC + 2 * c + 1));
        }
        if (tid < 20) bp[tid] = pk2(bc[2 * tid], bc[2 * tid + 1]);
        __syncthreads();

        int row = blockIdx.x * 128 + (tid >> 1);
        int half = tid & 1;                 // 0: cols 0..19, 1: cols 20..39
        float phi[RK];
#pragma unroll
        for (int k = 0; k < RK; k++) phi[k] = g_phi[(long)row * RK + k];
        float den = 0.f;
#pragma unroll
        for (int k = 0; k < RK; k++) den += phi[k] * Ts[k * 65 + 64];
        float dinv = 1.f / den;
#pragma unroll
        for (int k = 0; k < RK; k++) phi[k] *= dinv;

        u64t o[10];
#pragma unroll
        for (int c = 0; c < 10; c++) o[c] = bp[half * 10 + c];
        const float* h = g_h2 + (long)row * ND;
#pragma unroll 2
        for (int d = 0; d < ND; d++) {
            float hv = __ldg(h + d);
            float zd = 0.f;
#pragma unroll
            for (int k = 0; k < RK; k++) zd += phi[k] * Ts[k * 65 + d];
            u64t hv2 = pk2(hv, hv), zd2 = pk2(zd, zd);
            const u64t* w1 = Wp + d * 20 + half * 10;
            const u64t* w2 = Wp + (ND + d) * 20 + half * 10;
#pragma unroll
            for (int c = 0; c < 10; c++) {
                ffma2(o[c], hv2, w1[c]);
                ffma2(o[c], zd2, w2[c]);
            }
        }
        float* op = out + (long)row * NC + half * 20;
#pragma unroll
        for (int c = 0; c < 5; c++) {
            float v0, v1, v2, v3;
            upk2(o[2 * c], v0, v1);
            upk2(o[2 * c + 1], v2, v3);
            reinterpret_cast<float4*>(op)[c] = make_float4(v0, v1, v2, v3);
        }
        if (half == 0) g_deg[row] = 0;   // restore invariant for next call
    }
}

// ---------------- PDL launch helper ------------------------------------------
template <typename F, typename... Args>
static inline void pdl_launch(F* func, unsigned grid, unsigned block, Args... args) {
    cudaLaunchConfig_t cfg = {};
    cfg.gridDim = dim3(grid, 1, 1);
    cfg.blockDim = dim3(block, 1, 1);
    cfg.dynamicSmemBytes = 0;
    cfg.stream = 0;
    cudaLaunchAttribute at[1];
    at[0].id = cudaLaunchAttributeProgrammaticStreamSerialization;
    at[0].val.programmaticStreamSerializationAllowed = 1;
    cfg.attrs = at;
    cfg.numAttrs = 1;
    cudaLaunchKernelEx(&cfg, func, args...);
}

// ---------------------------------------------------------------------------
extern "C" void kernel_launch(void* const* d_in, const int* in_sizes, int n_in,
                              void* d_out, int out_size) {
    const float* x   = (const float*)d_in[0];
    const int*   ei  = (const int*)d_in[1];
    const float* W1l = (const float*)d_in[2];
    const float* b1  = (const float*)d_in[3];
    const float* W1r = (const float*)d_in[4];
    const float* W2l = (const float*)d_in[5];
    const float* b2  = (const float*)d_in[6];
    const float* W2r = (const float*)d_in[7];
    const float* aux = (const float*)d_in[8];
    const float* Wc  = (const float*)d_in[9];
    const float* bc  = (const float*)d_in[10];
    float* out = (float*)d_out;

    // 1) gemm1 (x@[W1l|W1r]) concurrently with ELL build
    fused1<<<NN / 64 + NE / 256, 256>>>(x, W1l, W1r, ei);
    // 2) layer-1 gather+epi (zeroes g_T)  [PDL]
    pdl_launch(gather1_kernel, NN / 16, 256, b1);
    // 3) gemm2  [PDL]
    pdl_launch(gemm2_kernel, NN / 64, 256, W2l, W2r);
    // 4) layer-2 gather+epi + phi  [PDL]
    pdl_launch(gather2_kernel, NN / 16, 256, b2, aux);
    // 5) fused phiT -> barrier -> classifier (+ g_deg reset)  [PDL]
    pdl_launch(tail2, 128, 256, Wc, bc, out);
}

// round 12
// speedup vs baseline: 1.0652x; 1.0652x over previous
#include <cuda_runtime.h>
#include <math.h>

#define NN 16384
#define NE 262144
#define NF 128
#define ND 64
#define NC 40
#define RK 16
#define MAXDEG 64
#define ZOFF16 (NN * 16)   // float4-unit offset of the permanent zero row

typedef unsigned long long u64t;

// ---------------- packed f32x2 helpers (Blackwell) --------------------------
__device__ __forceinline__ u64t pk2(float lo, float hi) {
    u64t r; asm("mov.b64 %0, {%1, %2};" : "=l"(r) : "f"(lo), "f"(hi)); return r;
}
__device__ __forceinline__ void upk2(u64t v, float& lo, float& hi) {
    asm("mov.b64 {%0, %1}, %2;" : "=f"(lo), "=f"(hi) : "l"(v));
}
__device__ __forceinline__ void ffma2(u64t& d, u64t a, u64t b) {
    asm("fma.rn.f32x2 %0, %1, %2, %0;" : "+l"(d) : "l"(a), "l"(b));
}
__device__ __forceinline__ void fadd2(u64t& d, u64t a) {
    asm("add.rn.f32x2 %0, %0, %1;" : "+l"(d) : "l"(a));
}
__device__ __forceinline__ void pdl_wait() {
    asm volatile("griddepcontrol.wait;" ::: "memory");
}

// ------------- scratch (device globals; zero at module load) ----------------
__device__ float g_xl [(NN + 1) * ND];   // row NN: permanent zero row
__device__ float g_xr [NN * ND];
__device__ float g_h1 [NN * ND];
__device__ float g_h1l[(NN + 1) * ND];   // row NN: permanent zero row
__device__ float g_h1r[NN * ND];
__device__ float g_h2 [NN * ND];
__device__ float g_phi[NN * RK];
__device__ float g_T  [RK * 65];
__device__ int   g_deg[NN];              // zero at load; tail2 re-zeros
__device__ int   g_ell[NN * MAXDEG];     // stores src*16 (float4-unit offsets)
__device__ unsigned g_sync;              // monotonic barrier counter

// c_k = sqrt(2^k / k!)
__constant__ float c_coef[RK] = {
    1.0f,          1.41421356f,  1.41421356f,  1.15470054f,
    0.81649658f,   0.51639778f,  0.29814240f,  0.15936387f,
    0.07968194f,   0.03756241f,  0.01679842f,  0.00716286f,
    0.00292422f,   0.00114698f,  4.33517e-4f,  1.58298e-4f};

// ---------------- grid-wide barrier (monotonic counter, no reset) -----------
__device__ __forceinline__ void grid_sync(unsigned G) {
    __syncthreads();
    if (threadIdx.x == 0) {
        __threadfence();
        unsigned old = atomicAdd(&g_sync, 1u);
        unsigned target = old / G * G + G;
        while ((int)(*(volatile unsigned*)&g_sync - target) < 0) {
            __nanosleep(64);
        }
        __threadfence();
    }
    __syncthreads();
}

// ---- dual GEMM body: outl = A @ Wl, outr = A @ Wr  (A:[NN,K], W:[K,64]) ----
// R9-proven form: float4 smem reads, pack-in-loop FFMA2.
template <int K>
__device__ __forceinline__ void gemm_body(const float* __restrict__ A,
                                          const float* __restrict__ Wl,
                                          const float* __restrict__ Wr,
                                          float* __restrict__ outl,
                                          float* __restrict__ outr,
                                          int mblk, float* sA, float* sW) {
    constexpr int KC = 16;
    const int tid = threadIdx.x;
    const int mg = tid >> 4;
    const int ng = tid & 15;
    const int m_base = mblk * 64;

    u64t acc[4][4];
#pragma unroll
    for (int i = 0; i < 4; i++)
#pragma unroll
        for (int j = 0; j < 4; j++) acc[i][j] = 0ull;

    for (int kk = 0; kk < K; kk += KC) {
        __syncthreads();
#pragma unroll
        for (int j = 0; j < 4; j++) {
            int i = tid + 256 * j;
            int m = i >> 4;
            int k = i & 15;
            sA[k * 68 + m] = __ldg(A + (long)(m_base + m) * K + kk + k);
        }
#pragma unroll
        for (int j = 0; j < 8; j++) {
            int i = tid + 256 * j;
            int k = i >> 7;
            int n = i & 127;
            float w = (n < 64) ? __ldg(Wl + (long)(kk + k) * 64 + n)
                               : __ldg(Wr + (long)(kk + k) * 64 + (n - 64));
            sW[k * 128 + n] = w;
        }
        __syncthreads();

#pragma unroll
        for (int k = 0; k < KC; k++) {
            float4 a = *reinterpret_cast<const float4*>(sA + k * 68 + mg * 4);
            const float4* w4 = reinterpret_cast<const float4*>(sW + k * 128);
            float4 w0 = w4[ng * 2], w1 = w4[ng * 2 + 1];
            u64t wp[4] = {pk2(w0.x, w0.y), pk2(w0.z, w0.w),
                          pk2(w1.x, w1.y), pk2(w1.z, w1.w)};
            u64t ap[4] = {pk2(a.x, a.x), pk2(a.y, a.y),
                          pk2(a.z, a.z), pk2(a.w, a.w)};
#pragma unroll
            for (int i = 0; i < 4; i++)
#pragma unroll
                for (int j = 0; j < 4; j++) ffma2(acc[i][j], ap[i], wp[j]);
        }
    }

    float* outp = (ng < 8) ? outl : outr;
    int cb = (ng & 7) * 8;
#pragma unroll
    for (int i = 0; i < 4; i++) {
        long r = m_base + mg * 4 + i;
        float o0, o1, o2, o3, o4v, o5, o6, o7;
        upk2(acc[i][0], o0, o1); upk2(acc[i][1], o2, o3);
        upk2(acc[i][2], o4v, o5); upk2(acc[i][3], o6, o7);
        float4* o4 = reinterpret_cast<float4*>(outp + r * ND + cb);
        o4[0] = make_float4(o0, o1, o2, o3);
        o4[1] = make_float4(o4v, o5, o6, o7);
    }
}

// ---- half-warp gather: warp handles 2 rows, 16 lanes per row, float4 -------
// batch-4 loads (proven best: 32 regs, occ ~72%)
template <bool RELU, bool PHI>
__device__ __forceinline__ void gather2rows(int base_row,
                                            const float* __restrict__ val,
                                            const float* __restrict__ selfp,
                                            const float* __restrict__ bias,
                                            float* __restrict__ out,
                                            float ainv, const float4* aux4s) {
    int lane = threadIdx.x & 31;
    int hsel = lane & 16;        // 0 or 16
    int lane16 = lane & 15;
    int row = base_row + (lane >> 4);
    int deg = __ldg(g_deg + row);
    const ulonglong2* v16 = reinterpret_cast<const ulonglong2*>(val);

    u64t a0 = 0ull, a1 = 0ull, a2 = 0ull, a3 = 0ull;
#pragma unroll 1
    for (int c = 0; c < MAXDEG; c += 16) {
        int dc = min(max(deg - c, 0), 16);
        int kmax = max(dc, __shfl_xor_sync(0xffffffffu, dc, 16));
        if (kmax == 0) break;
        int j = (lane16 < dc) ? __ldg(g_ell + row * MAXDEG + c + lane16) : ZOFF16;
        int kr = (kmax + 3) & ~3;
#pragma unroll 1
        for (int k = 0; k < kr; k += 4) {
            int b0 = __shfl_sync(0xffffffffu, j, hsel + k);
            int b1 = __shfl_sync(0xffffffffu, j, hsel + k + 1);
            int b2 = __shfl_sync(0xffffffffu, j, hsel + k + 2);
            int b3 = __shfl_sync(0xffffffffu, j, hsel + k + 3);
            ulonglong2 x0 = __ldg(v16 + b0 + lane16);
            ulonglong2 x1 = __ldg(v16 + b1 + lane16);
            ulonglong2 x2 = __ldg(v16 + b2 + lane16);
            ulonglong2 x3 = __ldg(v16 + b3 + lane16);
            fadd2(a0, x0.x); fadd2(a1, x0.y);
            fadd2(a2, x1.x); fadd2(a3, x1.y);
            fadd2(a0, x2.x); fadd2(a1, x2.y);
            fadd2(a2, x3.x); fadd2(a3, x3.y);
        }
    }
    fadd2(a0, a2); fadd2(a1, a3);

    float f0, f1, f2, f3;
    upk2(a0, f0, f1); upk2(a1, f2, f3);
    float inv = 1.f / fmaxf((float)deg, 1.f);
    float4 b = __ldg(reinterpret_cast<const float4*>(bias) + lane16);
    float4 s = __ldg(reinterpret_cast<const float4*>(selfp) + row * 16 + lane16);
    float4 r = make_float4(f0 * inv + b.x + s.x, f1 * inv + b.y + s.y,
                           f2 * inv + b.z + s.z, f3 * inv + b.w + s.w);
    if (RELU) {
        r.x = fmaxf(r.x, 0.f); r.y = fmaxf(r.y, 0.f);
        r.z = fmaxf(r.z, 0.f); r.w = fmaxf(r.w, 0.f);
    }
    reinterpret_cast<float4*>(out)[row * 16 + lane16] = r;

    if (PHI) {
        float4 av = aux4s[lane16];
        float dot = r.x * av.x + r.y * av.y + r.z * av.z + r.w * av.w;
        float nn2 = r.x * r.x + r.y * r.y + r.z * r.z + r.w * r.w;
#pragma unroll
        for (int o = 8; o; o >>= 1) {              // reduce within each half
            dot += __shfl_xor_sync(0xffffffffu, dot, o);
            nn2 += __shfl_xor_sync(0xffffffffu, nn2, o);
        }
        float sc = dot * ainv / fmaxf(sqrtf(nn2), 1e-8f);
        float e = expf(-sc * sc);
        float sc2 = sc * sc, sc4 = sc2 * sc2, sc8 = sc4 * sc4;
        float p = 1.f;
        if (lane16 & 1) p *= sc;
        if (lane16 & 2) p *= sc2;
        if (lane16 & 4) p *= sc4;
        if (lane16 & 8) p *= sc8;
        g_phi[row * RK + lane16] = e * c_coef[lane16] * p;
    }
}

// ---- launch 1: blocks [0,256) gemm1, blocks [256,1280) ELL fill ------------
__global__ __launch_bounds__(256) void fused1(const float* __restrict__ x,
                                              const float* __restrict__ W1l,
                                              const float* __restrict__ W1r,
                                              const int* __restrict__ ei) {
    __shared__ __align__(16) float sA[16 * 68];
    __shared__ __align__(16) float sW[16 * 128];
    if (blockIdx.x < NN / 64) {
        gemm_body<NF>(x, W1l, W1r, g_xl, g_xr, blockIdx.x, sA, sW);
    } else {
        int t = (blockIdx.x - NN / 64) * 256 + threadIdx.x;
        int src = __ldg(ei + t);
        int dst = __ldg(ei + NE + t);
        int slot = atomicAdd(g_deg + dst, 1) & (MAXDEG - 1);
        g_ell[dst * MAXDEG + slot] = src * 16;
    }
}

// ---- launch 2: layer-1 gather + relu epilogue (also zeroes g_T) ------------
__global__ __launch_bounds__(256) void gather1_kernel(const float* __restrict__ b1) {
    pdl_wait();
    if (blockIdx.x == 0)
        for (int i = threadIdx.x; i < RK * 65; i += 256) g_T[i] = 0.f;
    int base = (blockIdx.x * 8 + (threadIdx.x >> 5)) * 2;
    gather2rows<true, false>(base, g_xl, g_xr, b1, g_h1, 0.f, nullptr);
}

// ---- launch 3: gemm2 --------------------------------------------------------
__global__ __launch_bounds__(256) void gemm2_kernel(const float* __restrict__ W2l,
                                                    const float* __restrict__ W2r) {
    pdl_wait();
    __shared__ __align__(16) float sA[16 * 68];
    __shared__ __align__(16) float sW[16 * 128];
    gemm_body<ND>(g_h1, W2l, W2r, g_h1l, g_h1r, blockIdx.x, sA, sW);
}

// ---- launch 4: layer-2 gather + epilogue + phi ------------------------------
__global__ __launch_bounds__(256) void gather2_kernel(const float* __restrict__ b2,
                                                      const float* __restrict__ aux) {
    pdl_wait();
    __shared__ float4 aux4s[16];
    __shared__ float s_ainv;
    int tid = threadIdx.x;
    if (tid < 16) aux4s[tid] = __ldg(reinterpret_cast<const float4*>(aux) + tid);
    __syncthreads();
    if (tid < 16) {
        float4 a = aux4s[tid];
        float ss = a.x * a.x + a.y * a.y + a.z * a.z + a.w * a.w;
#pragma unroll
        for (int o = 8; o; o >>= 1) ss += __shfl_xor_sync(0x0000ffffu, ss, o);
        if (tid == 0) s_ainv = 1.f / fmaxf(sqrtf(ss), 1e-8f);
    }
    __syncthreads();
    int base = (blockIdx.x * 8 + (tid >> 5)) * 2;
    gather2rows<false, true>(base, g_h1l, g_h1r, b2, g_h2, s_ainv, aux4s);
}

// ---- launch 5 (fused): phiT -> grid barrier -> classifier -------------------
// 128 blocks x 256 threads. Stage E: 1024 warp-units x 16 rows.
// Stage F: 2 threads per row (128 rows per block).
__global__ __launch_bounds__(256) void tail2(const float* __restrict__ Wc,
                                             const float* __restrict__ bc,
                                             float* __restrict__ out) {
    pdl_wait();
    __shared__ __align__(16) float sp[6300];
    int tid = threadIdx.x;
    int lane = tid & 31;

    // ---- stage E: T = Phi^T [h2 | 1] ----------------------------------------
    {
        int gw = blockIdx.x * 8 + (tid >> 5);   // 1024 units x 16 rows
        float accA[RK], accB[RK];
#pragma unroll
        for (int k = 0; k < RK; k++) { accA[k] = 0.f; accB[k] = 0.f; }
        float accD = 0.f;
        int r0 = gw * 16;
#pragma unroll 2
        for (int r = r0; r < r0 + 16; r++) {
            float pv = (lane < RK) ? g_phi[(long)r * RK + lane] : 0.f;
            float v0 = g_h2[(long)r * ND + lane];
            float v1 = g_h2[(long)r * ND + 32 + lane];
            accD += pv;
#pragma unroll
            for (int k = 0; k < RK; k++) {
                float pk = __shfl_sync(0xffffffffu, pv, k);
                accA[k] += pk * v0;
                accB[k] += pk * v1;
            }
        }
#pragma unroll
        for (int k = 0; k < RK; k++) {
            atomicAdd(&g_T[k * 65 + lane], accA[k]);
            atomicAdd(&g_T[k * 65 + 32 + lane], accB[k]);
        }
        if (lane < RK) atomicAdd(&g_T[lane * 65 + 64], accD);
    }

    grid_sync(128);

    // ---- stage F: z = Phi T / den; out = [h2|z] @ Wc + bc; g_deg reset ------
    {
        float* Ts = sp;                                 // 1040 floats
        u64t* Wp = reinterpret_cast<u64t*>(sp + 1056);  // 2560 u64
        u64t* bp = reinterpret_cast<u64t*>(sp + 6176);  // 20 u64
        for (int i = tid; i < RK * 65; i += 256) Ts[i] = g_T[i];
        for (int i = tid; i < 128 * 20; i += 256) {
            int d = i / 20, c = i % 20;
            Wp[i] = pk2(__ldg(Wc + d * NC + 2 * c), __ldg(Wc + d * NC + 2 * c + 1));
        }
        if (tid < 20) bp[tid] = pk2(bc[2 * tid], bc[2 * tid + 1]);
        __syncthreads();

        int row = blockIdx.x * 128 + (tid >> 1);
        int half = tid & 1;                 // 0: cols 0..19, 1: cols 20..39
        float phi[RK];
#pragma unroll
        for (int k = 0; k < RK; k++) phi[k] = g_phi[(long)row * RK + k];
        float den = 0.f;
#pragma unroll
        for (int k = 0; k < RK; k++) den += phi[k] * Ts[k * 65 + 64];
        float dinv = 1.f / den;
#pragma unroll
        for (int k = 0; k < RK; k++) phi[k] *= dinv;

        u64t o[10];
#pragma unroll
        for (int c = 0; c < 10; c++) o[c] = bp[half * 10 + c];
        const float* h = g_h2 + (long)row * ND;
#pragma unroll 2
        for (int d = 0; d < ND; d++) {
            float hv = __ldg(h + d);
            float zd = 0.f;
#pragma unroll
            for (int k = 0; k < RK; k++) zd += phi[k] * Ts[k * 65 + d];
            u64t hv2 = pk2(hv, hv), zd2 = pk2(zd, zd);
            const u64t* w1 = Wp + d * 20 + half * 10;
            const u64t* w2 = Wp + (ND + d) * 20 + half * 10;
#pragma unroll
            for (int c = 0; c < 10; c++) {
                ffma2(o[c], hv2, w1[c]);
                ffma2(o[c], zd2, w2[c]);
            }
        }
        float* op = out + (long)row * NC + half * 20;
#pragma unroll
        for (int c = 0; c < 5; c++) {
            float v0, v1, v2, v3;
            upk2(o[2 * c], v0, v1);
            upk2(o[2 * c + 1], v2, v3);
            reinterpret_cast<float4*>(op)[c] = make_float4(v0, v1, v2, v3);
        }
        if (half == 0) g_deg[row] = 0;   // restore invariant for next call
    }
}

// ---------------- PDL launch helper ------------------------------------------
template <typename F, typename... Args>
static inline void pdl_launch(F* func, unsigned grid, unsigned block, Args... args) {
    cudaLaunchConfig_t cfg = {};
    cfg.gridDim = dim3(grid, 1, 1);
    cfg.blockDim = dim3(block, 1, 1);
    cfg.dynamicSmemBytes = 0;
    cfg.stream = 0;
    cudaLaunchAttribute at[1];
    at[0].id = cudaLaunchAttributeProgrammaticStreamSerialization;
    at[0].val.programmaticStreamSerializationAllowed = 1;
    cfg.attrs = at;
    cfg.numAttrs = 1;
    cudaLaunchKernelEx(&cfg, func, args...);
}

// ---------------------------------------------------------------------------
extern "C" void kernel_launch(void* const* d_in, const int* in_sizes, int n_in,
                              void* d_out, int out_size) {
    const float* x   = (const float*)d_in[0];
    const int*   ei  = (const int*)d_in[1];
    const float* W1l = (const float*)d_in[2];
    const float* b1  = (const float*)d_in[3];
    const float* W1r = (const float*)d_in[4];
    const float* W2l = (const float*)d_in[5];
    const float* b2  = (const float*)d_in[6];
    const float* W2r = (const float*)d_in[7];
    const float* aux = (const float*)d_in[8];
    const float* Wc  = (const float*)d_in[9];
    const float* bc  = (const float*)d_in[10];
    float* out = (float*)d_out;

    // 1) gemm1 (x@[W1l|W1r]) concurrently with ELL build
    fused1<<<NN / 64 + NE / 256, 256>>>(x, W1l, W1r, ei);
    // 2) layer-1 gather+epi (zeroes g_T)  [PDL]
    pdl_launch(gather1_kernel, NN / 16, 256, b1);
    // 3) gemm2  [PDL]
    pdl_launch(gemm2_kernel, NN / 64, 256, W2l, W2r);
    // 4) layer-2 gather+epi + phi  [PDL]
    pdl_launch(gather2_kernel, NN / 16, 256, b2, aux);
    // 5) fused phiT -> barrier -> classifier (+ g_deg reset)  [PDL]
    pdl_launch(tail2, 128, 256, Wc, bc, out);
}